// round 3
// baseline (speedup 1.0000x reference)
#include <cuda_runtime.h>

// Swin WindowAttention fused kernel, fp32 with packed fma.rn.f32x2 GEMM cores.
// B=4096 windows, N=49 tokens, C=128, 4 heads x 32, nW=64 masks.

#define NTOK   49
#define DIMC   128
#define NH     4
#define HD     32
#define NWIN   64
#define QKSCALE 0.17677669529663687f   // 32^-0.5

#define ST     58        // transposed x/O row stride (floats, even for LDS.64)
#define WTS    132       // staged transposed-weight row stride (floats, even)
#define AST    52        // attn / kT row stride (floats, even)

// shared memory layout (floats)
#define OFF_XT   0                          // 7424  : xT -> kT -> OT
#define OFF_W    (128*ST)                   // 16896 : W^T chunk -> attn S/P
#define OFF_QKV  (OFF_W + DIMC*WTS)         // 18816 : qkv -> proj W^T
#define SMEM_FLOATS (OFF_QKV + NTOK*384)    // 43136 floats = 172,544 B

typedef unsigned long long ull;

__device__ __forceinline__ ull splat2(float x) {
    ull r; unsigned u = __float_as_uint(x);
    asm("mov.b64 %0, {%1, %1};" : "=l"(r) : "r"(u));
    return r;
}
__device__ __forceinline__ void ffma2(ull& a, ull x, ull y) {
    asm("fma.rn.f32x2 %0, %1, %2, %0;" : "+l"(a) : "l"(x), "l"(y));
}
__device__ __forceinline__ float2 unpack2(ull v) {
    unsigned lo, hi;
    asm("mov.b64 {%0, %1}, %2;" : "=r"(lo), "=r"(hi) : "l"(v));
    return make_float2(__uint_as_float(lo), __uint_as_float(hi));
}

// Precombined (bias + mask) per (window-in-image, head): 64*4*49*49 floats = 2.46 MB
__device__ float g_cmb[NWIN * NH * NTOK * NTOK];

__global__ void prep_bias_kernel(const float* __restrict__ mask,
                                 const float* __restrict__ bias_table,
                                 const int*   __restrict__ rel_index) {
    int idx = blockIdx.x * 256 + threadIdx.x;
    if (idx >= NWIN * NH * NTOK * NTOK) return;
    int w  = idx / (NH * NTOK * NTOK);
    int r  = idx % (NH * NTOK * NTOK);
    int h  = r / (NTOK * NTOK);
    int ij = r % (NTOK * NTOK);
    g_cmb[idx] = bias_table[rel_index[ij] * NH + h] + mask[w * NTOK * NTOK + ij];
}

__global__ __launch_bounds__(256, 1)
void win_attn_kernel(const float* __restrict__ x,
                     const float* __restrict__ qkv_w,
                     const float* __restrict__ qkv_b,
                     const float* __restrict__ proj_w,
                     const float* __restrict__ proj_b,
                     float* __restrict__ out) {
    extern __shared__ float sm[];
    float* sxT  = sm + OFF_XT;    // xT[k][r] -> kT[d][j] -> OT[c][r]
    float* sw   = sm + OFF_W;     // W^T chunk [k][c] -> attn S/P
    float* sqkv = sm + OFF_QKV;   // qkv (49 x 384) -> proj W^T

    const int tid = threadIdx.x;
    const int tx  = tid & 31;
    const int ty  = tid >> 5;            // warp id 0..7
    const int g   = ty >> 1;             // row group 0..3 (14 rows each)
    const int cs  = (ty & 1) * 32 + tx;  // column-slot 0..63 (2 cols each)
    const int b   = blockIdx.x;

    // ---------- load x transposed: sxT[c][r] ----------
    {
        const float4* xg = (const float4*)(x + (size_t)b * NTOK * DIMC);
        #pragma unroll
        for (int it = 0; it < 7; it++) {
            int i = tid + it * 256;             // over 49*32 float4
            if (i < NTOK * 32) {
                float4 v = xg[i];
                int r  = i >> 5;
                int c4 = (i & 31) * 4;
                sxT[(c4 + 0) * ST + r] = v.x;
                sxT[(c4 + 1) * ST + r] = v.y;
                sxT[(c4 + 2) * ST + r] = v.z;
                sxT[(c4 + 3) * ST + r] = v.w;
            }
        }
    }

    // ---------- qkv = x @ W^T + b  (3 chunks of 128 cols), f32x2 ----------
    for (int ch = 0; ch < 3; ch++) {
        if (ch) __syncthreads();   // protect sw reuse
        {   // stage W chunk transposed: sw[k][c]
            const float4* wg = (const float4*)(qkv_w + (size_t)ch * 128 * DIMC);
            #pragma unroll
            for (int it = 0; it < 16; it++) {
                int idx = tid + it * 256;
                int c   = idx >> 5;
                int kq  = idx & 31;
                float4 v = wg[c * 32 + kq];
                sw[(4 * kq + 0) * WTS + c] = v.x;
                sw[(4 * kq + 1) * WTS + c] = v.y;
                sw[(4 * kq + 2) * WTS + c] = v.z;
                sw[(4 * kq + 3) * WTS + c] = v.w;
            }
        }
        __syncthreads();

        ull acc[7][2];
        #pragma unroll
        for (int p = 0; p < 7; p++) { acc[p][0] = 0ull; acc[p][1] = 0ull; }

        const float* xbase = sxT + 14 * g;
        #pragma unroll 4
        for (int k = 0; k < DIMC; k++) {
            ull xp[7];
            #pragma unroll
            for (int p = 0; p < 7; p++)
                xp[p] = *(const ull*)(xbase + k * ST + 2 * p);   // rows (2p,2p+1), warp-uniform
            float2 wv = *(const float2*)(&sw[k * WTS + 2 * cs]);
            ull d0 = splat2(wv.x), d1 = splat2(wv.y);
            #pragma unroll
            for (int p = 0; p < 7; p++) {
                ffma2(acc[p][0], xp[p], d0);
                ffma2(acc[p][1], xp[p], d1);
            }
        }

        float2 bb  = *(const float2*)(qkv_b + ch * 128 + 2 * cs);
        float  scl = (ch == 0) ? QKSCALE : 1.f;   // fold attn scale into q
        #pragma unroll
        for (int p = 0; p < 7; p++) {
            int r0 = 14 * g + 2 * p;
            float2 v0 = unpack2(acc[p][0]);
            float2 v1 = unpack2(acc[p][1]);
            if (r0 < NTOK)
                *(float2*)&sqkv[r0 * 384 + ch * 128 + 2 * cs] =
                    make_float2((v0.x + bb.x) * scl, (v1.x + bb.y) * scl);
            if (r0 + 1 < NTOK)
                *(float2*)&sqkv[(r0 + 1) * 384 + ch * 128 + 2 * cs] =
                    make_float2((v0.y + bb.x) * scl, (v1.y + bb.y) * scl);
        }
    }
    __syncthreads();

    // ---------- transpose K into sxT region: kT[d][j] ----------
    {
        for (int it = 0; it < 25; it++) {
            int idx = tid + it * 256;             // over 49*128
            if (idx < NTOK * DIMC) {
                int j   = idx >> 7;
                int hdd = idx & 127;
                sxT[hdd * AST + j] = sqkv[j * 384 + 128 + hdd];
            }
        }
    }
    __syncthreads();

    // ---------- S = q @ kT + (bias+mask), into sw region (f32x2 over col pairs) ----------
    {
        int h = ty >> 1, io = ty & 1;
        const float* cm  = g_cmb + (size_t)((b & (NWIN - 1)) * NH + h) * (NTOK * NTOK);
        const float* kTb = sxT;
        int c0 = 2 * tx, c1 = 2 * tx + 1;
        for (int i = io; i < NTOK; i += 2) {
            const float* qrow = sqkv + i * 384 + h * HD;
            ull acc = 0ull;
            #pragma unroll
            for (int d = 0; d < HD; d++) {
                ull qd = splat2(qrow[d]);                              // broadcast
                ull kp = *(const ull*)(kTb + (h * HD + d) * AST + c0); // cols (c0,c1)
                ffma2(acc, qd, kp);
            }
            float2 a = unpack2(acc);
            float* srow = sw + (h * NTOK + i) * AST;
            if (c0 < NTOK) srow[c0] = a.x + cm[i * NTOK + c0];
            if (c1 < NTOK) srow[c1] = a.y + cm[i * NTOK + c1];
        }
    }
    __syncthreads();

    // ---------- softmax rows (in place) ----------
    {
        int h = ty >> 1, io = ty & 1;
        for (int i = io; i < NTOK; i += 2) {
            float* row = sw + (h * NTOK + i) * AST;
            float v0 = row[tx];
            float v1 = (tx < NTOK - 32) ? row[tx + 32] : -1e30f;
            float m  = fmaxf(v0, v1);
            #pragma unroll
            for (int o = 16; o; o >>= 1) m = fmaxf(m, __shfl_xor_sync(0xffffffffu, m, o));
            float e0 = __expf(v0 - m);
            float e1 = (tx < NTOK - 32) ? __expf(v1 - m) : 0.f;
            float s  = e0 + e1;
            #pragma unroll
            for (int o = 16; o; o >>= 1) s += __shfl_xor_sync(0xffffffffu, s, o);
            float inv = 1.f / s;
            row[tx] = e0 * inv;
            if (tx < NTOK - 32) row[tx + 32] = e1 * inv;
        }
    }
    __syncthreads();

    // ---------- O = P @ V, written TRANSPOSED into sxT region: OT[c][r] ----------
    {
        #pragma unroll
        for (int h = 0; h < NH; h++) {
            float acc[7];
            #pragma unroll
            for (int t = 0; t < 7; t++) acc[t] = 0.f;
            for (int j = 0; j < NTOK; j++) {
                float vv = sqkv[j * 384 + 256 + h * HD + tx];
                #pragma unroll
                for (int t = 0; t < 7; t++)
                    acc[t] = fmaf(sw[(h * NTOK + ty + 8 * t) * AST + j], vv, acc[t]);
            }
            #pragma unroll
            for (int t = 0; t < 7; t++) {
                int r = ty + 8 * t;
                if (r < NTOK) sxT[(h * HD + tx) * ST + r] = acc[t];
            }
        }
    }
    __syncthreads();

    // ---------- stage proj W^T into sqkv region (qkv dead) ----------
    {
        const float4* wg = (const float4*)proj_w;
        #pragma unroll
        for (int it = 0; it < 16; it++) {
            int idx = tid + it * 256;
            int c   = idx >> 5;
            int kq  = idx & 31;
            float4 v = wg[c * 32 + kq];
            sqkv[(4 * kq + 0) * WTS + c] = v.x;
            sqkv[(4 * kq + 1) * WTS + c] = v.y;
            sqkv[(4 * kq + 2) * WTS + c] = v.z;
            sqkv[(4 * kq + 3) * WTS + c] = v.w;
        }
    }
    __syncthreads();

    // ---------- out = O @ projW^T + b  (f32x2) ----------
    {
        ull acc[7][2];
        #pragma unroll
        for (int p = 0; p < 7; p++) { acc[p][0] = 0ull; acc[p][1] = 0ull; }

        const float* obase = sxT + 14 * g;
        #pragma unroll 4
        for (int k = 0; k < DIMC; k++) {
            ull xp[7];
            #pragma unroll
            for (int p = 0; p < 7; p++)
                xp[p] = *(const ull*)(obase + k * ST + 2 * p);
            float2 wv = *(const float2*)(&sqkv[k * WTS + 2 * cs]);
            ull d0 = splat2(wv.x), d1 = splat2(wv.y);
            #pragma unroll
            for (int p = 0; p < 7; p++) {
                ffma2(acc[p][0], xp[p], d0);
                ffma2(acc[p][1], xp[p], d1);
            }
        }

        float2 bb = *(const float2*)(proj_b + 2 * cs);
        float* outb = out + (size_t)b * NTOK * DIMC;
        #pragma unroll
        for (int p = 0; p < 7; p++) {
            int r0 = 14 * g + 2 * p;
            float2 v0 = unpack2(acc[p][0]);
            float2 v1 = unpack2(acc[p][1]);
            if (r0 < NTOK)
                *(float2*)&outb[r0 * DIMC + 2 * cs] =
                    make_float2(v0.x + bb.x, v1.x + bb.y);
            if (r0 + 1 < NTOK)
                *(float2*)&outb[(r0 + 1) * DIMC + 2 * cs] =
                    make_float2(v0.y + bb.x, v1.y + bb.y);
        }
    }
}

extern "C" void kernel_launch(void* const* d_in, const int* in_sizes, int n_in,
                              void* d_out, int out_size) {
    const float* x          = (const float*)d_in[0];
    const float* mask       = (const float*)d_in[1];
    const float* qkv_w      = (const float*)d_in[2];
    const float* qkv_b      = (const float*)d_in[3];
    const float* proj_w     = (const float*)d_in[4];
    const float* proj_b     = (const float*)d_in[5];
    const float* bias_table = (const float*)d_in[6];
    const int*   rel_index  = (const int*)d_in[7];
    float* out = (float*)d_out;

    size_t smem = SMEM_FLOATS * sizeof(float);
    cudaFuncSetAttribute(win_attn_kernel,
                         cudaFuncAttributeMaxDynamicSharedMemorySize, (int)smem);

    int total = NWIN * NH * NTOK * NTOK;
    prep_bias_kernel<<<(total + 255) / 256, 256>>>(mask, bias_table, rel_index);
    win_attn_kernel<<<4096, 256, smem>>>(x, qkv_w, qkv_b, proj_w, proj_b, out);
}

// round 8
// speedup vs baseline: 1.9082x; 1.9082x over previous
#include <cuda_runtime.h>
#include <cuda_bf16.h>
#include <cstdint>

// Swin WindowAttention, 3-kernel pipeline (sm_100-safe: mma.sync, no tcgen05):
//   K1: mma.sync bf16x3-split GEMM  qkv = x @ Wqkv^T + b  -> g_qT/g_kT/g_vT (transposed per window)
//   K2: scalar attention per (window, head), packed f32x2 -> g_O
//   K3: mma.sync bf16x3-split GEMM  out = O @ Wproj^T + b -> d_out

#define NTOK     49
#define DIMC     128
#define NH       4
#define NWIN     64
#define NWINDOWS 4096
#define MROWS    (NWINDOWS * NTOK)   // 200704
#define MTILES   (MROWS / 128)       // 1568 (exact)
#define TPAD     52
#define QKSCALE  0.17677669529663687f

typedef unsigned long long ull;

// ------------------------- device globals (scratch) -------------------------
__device__ float g_qT[NWINDOWS * DIMC * TPAD];   // [win][c][tokpad]
__device__ float g_kT[NWINDOWS * DIMC * TPAD];
__device__ float g_vT[NWINDOWS * DIMC * TPAD];
__device__ float g_O [(size_t)MROWS * DIMC];     // [row][c]
__device__ float g_cmb[NWIN * NH * NTOK * TPAD]; // bias+mask, j padded to 52

// ------------------------- small helpers -------------------------
__device__ __forceinline__ uint32_t smem_u32(const void* p) {
    uint32_t a;
    asm("{ .reg .u64 t; cvta.to.shared.u64 t, %1; cvt.u32.u64 %0, t; }" : "=r"(a) : "l"(p));
    return a;
}
__device__ __forceinline__ ull splat2(float x) {
    ull r; unsigned u = __float_as_uint(x);
    asm("mov.b64 %0, {%1, %1};" : "=l"(r) : "r"(u));
    return r;
}
__device__ __forceinline__ void ffma2(ull& a, ull x, ull y) {
    asm("fma.rn.f32x2 %0, %1, %2, %0;" : "+l"(a) : "l"(x), "l"(y));
}
__device__ __forceinline__ float2 unpack2(ull v) {
    unsigned lo, hi;
    asm("mov.b64 {%0, %1}, %2;" : "=r"(lo), "=r"(hi) : "l"(v));
    return make_float2(__uint_as_float(lo), __uint_as_float(hi));
}
__device__ __forceinline__ void ldsm4(uint32_t* r, uint32_t addr) {
    asm volatile("ldmatrix.sync.aligned.m8n8.x4.shared.b16 {%0,%1,%2,%3}, [%4];"
                 : "=r"(r[0]), "=r"(r[1]), "=r"(r[2]), "=r"(r[3]) : "r"(addr));
}
__device__ __forceinline__ void mma16816(float* d, const uint32_t* a, const uint32_t* b) {
    asm volatile("mma.sync.aligned.m16n8k16.row.col.f32.bf16.bf16.f32 "
                 "{%0,%1,%2,%3}, {%4,%5,%6,%7}, {%8,%9}, {%0,%1,%2,%3};"
                 : "+f"(d[0]), "+f"(d[1]), "+f"(d[2]), "+f"(d[3])
                 : "r"(a[0]), "r"(a[1]), "r"(a[2]), "r"(a[3]), "r"(b[0]), "r"(b[1]));
}
// pack (a,b) to bf16x2 (b in high half), via PTX cvt only
__device__ __forceinline__ uint32_t cvt_bf16x2(float a, float b) {
    uint32_t r;
    asm("cvt.rn.bf16x2.f32 %0, %1, %2;" : "=r"(r) : "f"(b), "f"(a));
    return r;
}

// ------------------------- prep: bias+mask combined, padded stride -------------------------
__global__ void prep_cmb_kernel(const float* __restrict__ mask,
                                const float* __restrict__ bias_table,
                                const int*   __restrict__ rel_index) {
    int idx = blockIdx.x * 256 + threadIdx.x;
    if (idx >= NWIN * NH * NTOK * TPAD) return;
    int j = idx % TPAD;
    int rest = idx / TPAD;
    int i = rest % NTOK;
    int h = (rest / NTOK) % NH;
    int w = rest / (NTOK * NH);
    float v = 0.f;
    if (j < NTOK)
        v = bias_table[rel_index[i * NTOK + j] * NH + h] + mask[(w * NTOK + i) * NTOK + j];
    g_cmb[idx] = v;
}

// ------------------------- K1/K3: bf16x3 split GEMM via mma.sync -------------------------
// SMEM layout (bytes): A-hi / A-lo / B-hi / B-lo, each 128 rows x 136 bf16 (272 B stride).
// D bounce tile (128 x 129 fp32) overlays the B region after MMAs complete.
#define BSTRIDE   272                 // bytes per staged bf16 row
#define SM_AHI    0
#define SM_ALO    34816
#define SM_BHI    69632
#define SM_BLO    104448
#define SM_TOTAL  139264
#define DST       129                 // D bounce stride (fp32), conflict-free

// split (a,b) into hi/lo bf16x2 pairs; residual computed from packed hi bits
__device__ __forceinline__ void split2(float a, float b, uint32_t& h2, uint32_t& l2) {
    h2 = cvt_bf16x2(a, b);
    float af = __uint_as_float(h2 << 16);
    float bf = __uint_as_float(h2 & 0xFFFF0000u);
    l2 = cvt_bf16x2(a - af, b - bf);
}

__device__ __forceinline__ void stage_split(const float* __restrict__ src,  // 128x128 fp32
                                            char* hi, char* lo, int tid) {
    const float4* s4 = (const float4*)src;
    #pragma unroll
    for (int it = 0; it < 16; it++) {
        int i  = tid + it * 256;       // 0..4095 float4s
        int r  = i >> 5;
        int c4 = (i & 31) * 8;         // byte offset of first bf16x2 in row
        float4 v = s4[i];
        uint32_t h0, l0, h1, l1;
        split2(v.x, v.y, h0, l0);
        split2(v.z, v.w, h1, l1);
        ull hp, lp;
        asm("mov.b64 %0, {%1, %2};" : "=l"(hp) : "r"(h0), "r"(h1));
        asm("mov.b64 %0, {%1, %2};" : "=l"(lp) : "r"(l0), "r"(l1));
        *(ull*)(hi + r * BSTRIDE + c4) = hp;
        *(ull*)(lo + r * BSTRIDE + c4) = lp;
    }
}

__global__ __launch_bounds__(256, 1)
void gemm_split_kernel(const float* __restrict__ A,     // M x 128 fp32 (ignored if mode==1)
                       const float* __restrict__ W,     // (nchunks*128) x 128 fp32
                       const float* __restrict__ bias,  // nchunks*128
                       int nchunks, int mode,           // 0: qkv scatter, 1: proj->out
                       float* __restrict__ out) {
    extern __shared__ char gsm[];
    char* sAhi = gsm + SM_AHI;
    char* sAlo = gsm + SM_ALO;
    char* sBhi = gsm + SM_BHI;
    char* sBlo = gsm + SM_BLO;
    float* sD  = (float*)(gsm + SM_BHI);      // overlays B region

    const int tid = threadIdx.x, lane = tid & 31, wid = tid >> 5;
    const int wm = wid & 3;           // warp M block (32 rows)
    const int wn = wid >> 2;          // warp N block (64 cols)
    const int m0 = blockIdx.x * 128;
    const float* Ap = (mode == 1) ? g_O : A;

    stage_split(Ap + (size_t)m0 * 128, sAhi, sAlo, tid);

    // ldmatrix base addresses (bytes)
    const uint32_t aHiB = smem_u32(sAhi), aLoB = smem_u32(sAlo);
    const uint32_t bHiB = smem_u32(sBhi), bLoB = smem_u32(sBlo);
    // A tile mt: rows 32*wm + 16*mt + lane%16, col-half by lane/16
    uint32_t aOff[2];
    #pragma unroll
    for (int mt = 0; mt < 2; mt++)
        aOff[mt] = (uint32_t)((32 * wm + 16 * mt + (lane & 15)) * BSTRIDE + (lane >> 4) * 16);
    // B pair p: n rows 64*wn + 16*p + lane%8 + ((lane>=16)*8), k-half by (lane>>3)&1
    uint32_t bOff[4];
    #pragma unroll
    for (int p = 0; p < 4; p++)
        bOff[p] = (uint32_t)((64 * wn + 16 * p + (lane & 7) + ((lane >> 4) << 3)) * BSTRIDE
                             + ((lane >> 3) & 1) * 16);

    for (int ch = 0; ch < nchunks; ch++) {
        if (ch) __syncthreads();                       // sD readers done before B restage
        stage_split(W + (size_t)ch * 128 * 128, sBhi, sBlo, tid);
        __syncthreads();

        float acc[2][8][4];
        #pragma unroll
        for (int mt = 0; mt < 2; mt++)
            #pragma unroll
            for (int nt = 0; nt < 8; nt++)
                #pragma unroll
                for (int e = 0; e < 4; e++) acc[mt][nt][e] = 0.f;

        #pragma unroll
        for (int kk = 0; kk < 8; kk++) {
            const uint32_t kb = kk * 32;
            uint32_t ah[2][4], al[2][4], bh[4][4], bl[4][4];
            #pragma unroll
            for (int mt = 0; mt < 2; mt++) {
                ldsm4(ah[mt], aHiB + aOff[mt] + kb);
                ldsm4(al[mt], aLoB + aOff[mt] + kb);
            }
            #pragma unroll
            for (int p = 0; p < 4; p++) {
                ldsm4(bh[p], bHiB + bOff[p] + kb);
                ldsm4(bl[p], bLoB + bOff[p] + kb);
            }
            #pragma unroll
            for (int mt = 0; mt < 2; mt++)
                #pragma unroll
                for (int p = 0; p < 4; p++) {
                    mma16816(acc[mt][2 * p],     ah[mt], &bh[p][0]);   // hi*hi
                    mma16816(acc[mt][2 * p + 1], ah[mt], &bh[p][2]);
                    mma16816(acc[mt][2 * p],     ah[mt], &bl[p][0]);   // hi*lo
                    mma16816(acc[mt][2 * p + 1], ah[mt], &bl[p][2]);
                    mma16816(acc[mt][2 * p],     al[mt], &bh[p][0]);   // lo*hi
                    mma16816(acc[mt][2 * p + 1], al[mt], &bh[p][2]);
                }
        }
        __syncthreads();                               // MMAs done before D overlays B

        // accumulators -> sD
        #pragma unroll
        for (int mt = 0; mt < 2; mt++) {
            int r0 = 32 * wm + 16 * mt + (lane >> 2);
            #pragma unroll
            for (int nt = 0; nt < 8; nt++) {
                int n = 64 * wn + 8 * nt + 2 * (lane & 3);
                sD[r0 * DST + n]           = acc[mt][nt][0];
                sD[r0 * DST + n + 1]       = acc[mt][nt][1];
                sD[(r0 + 8) * DST + n]     = acc[mt][nt][2];
                sD[(r0 + 8) * DST + n + 1] = acc[mt][nt][3];
            }
        }
        __syncthreads();

        // coalesced global write
        const float* bb = bias + ch * 128;
        if (mode == 0) {
            float* base = (ch == 0) ? g_qT : (ch == 1 ? g_kT : g_vT);
            float scl = (ch == 0) ? QKSCALE : 1.f;
            #pragma unroll 4
            for (int it = 0; it < 64; it++) {
                int i = tid + it * 256;
                int c = i >> 7, m = i & 127;
                float v = (sD[m * DST + c] + __ldg(bb + c)) * scl;
                unsigned gm = (unsigned)(m0 + m);
                unsigned win = gm / 49u;
                unsigned tok = gm - win * 49u;
                base[((size_t)win * 128 + c) * TPAD + tok] = v;
            }
        } else {
            #pragma unroll 4
            for (int it = 0; it < 64; it++) {
                int i = tid + it * 256;
                int r = i >> 7, c = i & 127;
                out[(size_t)(m0 + r) * 128 + c] = sD[r * DST + c] + __ldg(bb + c);
            }
        }
    }
}

// ------------------------- K2: attention per (window, head) -------------------------
__global__ __launch_bounds__(128)
void attn_kernel() {
    __shared__ __align__(16) float qT_s[32 * TPAD];
    __shared__ __align__(16) float kT_s[32 * TPAD + 16];  // +pad for OOB lane reads
    __shared__ __align__(16) float v_s [25 * 64];         // [jp][c][2] interleaved
    __shared__ __align__(16) float S_s [NTOK * TPAD];

    const int tid = threadIdx.x, wid = tid >> 5, lane = tid & 31;
    const int win = blockIdx.x >> 2, h = blockIdx.x & 3;
    const size_t base = ((size_t)win * 128 + h * 32) * TPAD;

    // stage q/k (transposed slices) and v (jp-interleaved)
    for (int i = tid; i < 32 * TPAD; i += 128) {
        qT_s[i] = g_qT[base + i];
        kT_s[i] = g_kT[base + i];
    }
    for (int i = tid; i < 32 * 50; i += 128) {
        int c = i / 50, j = i % 50;
        float v = (j < NTOK) ? g_vT[base + c * TPAD + j] : 0.f;
        v_s[(j >> 1) * 64 + c * 2 + (j & 1)] = v;
    }
    __syncthreads();

    // ---- S = qT^T kT + cmb : i-pairs per warp, j-pairs per lane ----
    const float* cmb = g_cmb + (size_t)(((win & (NWIN - 1)) * NH + h)) * (NTOK * TPAD);
    for (int pr = wid; pr < 25; pr += 4) {
        int i0 = 2 * pr;
        ull a0 = 0ull, a1 = 0ull;
        #pragma unroll
        for (int d = 0; d < 32; d++) {
            ull qpv = *(const ull*)&qT_s[d * TPAD + i0];        // broadcast (i0,i0+1)
            float2 q = unpack2(qpv);
            ull kp = *(const ull*)&kT_s[d * TPAD + 2 * lane];   // j-pair per lane
            ffma2(a0, splat2(q.x), kp);
            ffma2(a1, splat2(q.y), kp);
        }
        if (lane < 25) {
            float2 c0 = *(const float2*)&cmb[i0 * TPAD + 2 * lane];
            float2 s0 = unpack2(a0);
            *(float2*)&S_s[i0 * TPAD + 2 * lane] = make_float2(s0.x + c0.x, s0.y + c0.y);
            if (i0 + 1 < NTOK) {
                float2 c1 = *(const float2*)&cmb[(i0 + 1) * TPAD + 2 * lane];
                float2 s1 = unpack2(a1);
                *(float2*)&S_s[(i0 + 1) * TPAD + 2 * lane] = make_float2(s1.x + c1.x, s1.y + c1.y);
            }
        }
    }
    __syncthreads();

    // ---- softmax rows (zero the padded cols 49..51 for PV) ----
    for (int i = wid; i < NTOK; i += 4) {
        float* row = S_s + i * TPAD;
        float v0 = row[lane];
        float v1 = (lane < NTOK - 32) ? row[lane + 32] : -1e30f;
        float m = fmaxf(v0, v1);
        #pragma unroll
        for (int o = 16; o; o >>= 1) m = fmaxf(m, __shfl_xor_sync(0xffffffffu, m, o));
        float e0 = __expf(v0 - m);
        float e1 = (lane < NTOK - 32) ? __expf(v1 - m) : 0.f;
        float s = e0 + e1;
        #pragma unroll
        for (int o = 16; o; o >>= 1) s += __shfl_xor_sync(0xffffffffu, s, o);
        float inv = 1.f / s;
        row[lane] = e0 * inv;
        if (lane < NTOK - 32)      row[lane + 32] = e1 * inv;
        else if (lane < NTOK - 29) row[lane + 32] = 0.f;   // cols 49,50,51 := 0
    }
    __syncthreads();

    // ---- O = P V : rows per warp, c per lane, j-pairs packed ----
    ull acc[13];
    #pragma unroll
    for (int t = 0; t < 13; t++) acc[t] = 0ull;
    for (int jp = 0; jp < 25; jp++) {
        ull vp = *(const ull*)&v_s[jp * 64 + 2 * lane];
        #pragma unroll
        for (int t = 0; t < 13; t++) {
            int i = wid + 4 * t;
            if (i < NTOK) {
                ull pp = *(const ull*)&S_s[i * TPAD + 2 * jp];   // broadcast
                ffma2(acc[t], pp, vp);
            }
        }
    }
    #pragma unroll
    for (int t = 0; t < 13; t++) {
        int i = wid + 4 * t;
        if (i < NTOK) {
            float2 a = unpack2(acc[t]);
            g_O[((size_t)win * NTOK + i) * 128 + h * 32 + lane] = a.x + a.y;
        }
    }
}

// ------------------------- launch -------------------------
extern "C" void kernel_launch(void* const* d_in, const int* in_sizes, int n_in,
                              void* d_out, int out_size) {
    const float* x          = (const float*)d_in[0];
    const float* mask       = (const float*)d_in[1];
    const float* qkv_w      = (const float*)d_in[2];
    const float* qkv_b      = (const float*)d_in[3];
    const float* proj_w     = (const float*)d_in[4];
    const float* proj_b     = (const float*)d_in[5];
    const float* bias_table = (const float*)d_in[6];
    const int*   rel_index  = (const int*)d_in[7];
    float* out = (float*)d_out;

    cudaFuncSetAttribute(gemm_split_kernel,
                         cudaFuncAttributeMaxDynamicSharedMemorySize, SM_TOTAL);

    int ctot = NWIN * NH * NTOK * TPAD;
    prep_cmb_kernel<<<(ctot + 255) / 256, 256>>>(mask, bias_table, rel_index);

    // K1: qkv GEMM -> g_qT/g_kT/g_vT
    gemm_split_kernel<<<MTILES, 256, SM_TOTAL>>>(x, qkv_w, qkv_b, 3, 0, out);
    // K2: attention -> g_O
    attn_kernel<<<NWINDOWS * NH, 128>>>();
    // K3: proj GEMM -> out
    gemm_split_kernel<<<MTILES, 256, SM_TOTAL>>>(nullptr, proj_w, proj_b, 1, 1, out);
}

// round 9
// speedup vs baseline: 3.3134x; 1.7364x over previous
#include <cuda_runtime.h>
#include <cuda_bf16.h>
#include <cstdint>

// Swin WindowAttention, 4-kernel pipeline, all-tensor-core (sm_100-safe mma.sync):
//   prep: bias+mask combined (stride 56, -1e30 pad for j>=49)
//   K1: bf16x3-split GEMM qkv = x@Wqkv^T + b -> q,k bf16 hi/lo [win][tok][128]; v hi/lo transposed [win][c][64]
//   K2: tensor-core attention per (window, head): S via mma (2-split), reg softmax, PV via mma (2-split)
//   K3: bf16x3-split GEMM out = O@Wproj^T + b

#define NTOK     49
#define DIMC     128
#define NH       4
#define NWIN     64
#define NWINDOWS 4096
#define MROWS    (NWINDOWS * NTOK)   // 200704
#define MTILES   (MROWS / 128)       // 1568
#define QKSCALE  0.17677669529663687f

typedef unsigned long long ull;

// ------------------------- device globals (scratch, zero-init .bss) -------------------------
__device__ uint32_t g_qh[(size_t)NWINDOWS * NTOK * 64];   // bf16x2 pairs, [win][tok][64]
__device__ uint32_t g_ql[(size_t)NWINDOWS * NTOK * 64];
__device__ uint32_t g_kh[(size_t)NWINDOWS * NTOK * 64];
__device__ uint32_t g_kl[(size_t)NWINDOWS * NTOK * 64];
__device__ unsigned short g_vh[(size_t)NWINDOWS * 128 * 64];  // bf16, [win][c][64] (j pad 49..63 stays 0)
__device__ unsigned short g_vl[(size_t)NWINDOWS * 128 * 64];
__device__ float g_O [(size_t)MROWS * DIMC];              // [row][c]
__device__ float g_cmb[NWIN * NH * NTOK * 56];            // [w][h][i][56], j>=49 -> -1e30

// ------------------------- helpers -------------------------
__device__ __forceinline__ uint32_t smem_u32(const void* p) {
    uint32_t a;
    asm("{ .reg .u64 t; cvta.to.shared.u64 t, %1; cvt.u32.u64 %0, t; }" : "=r"(a) : "l"(p));
    return a;
}
__device__ __forceinline__ void ldsm4(uint32_t* r, uint32_t addr) {
    asm volatile("ldmatrix.sync.aligned.m8n8.x4.shared.b16 {%0,%1,%2,%3}, [%4];"
                 : "=r"(r[0]), "=r"(r[1]), "=r"(r[2]), "=r"(r[3]) : "r"(addr));
}
__device__ __forceinline__ void mma16816(float* d, const uint32_t* a, const uint32_t* b) {
    asm volatile("mma.sync.aligned.m16n8k16.row.col.f32.bf16.bf16.f32 "
                 "{%0,%1,%2,%3}, {%4,%5,%6,%7}, {%8,%9}, {%0,%1,%2,%3};"
                 : "+f"(d[0]), "+f"(d[1]), "+f"(d[2]), "+f"(d[3])
                 : "r"(a[0]), "r"(a[1]), "r"(a[2]), "r"(a[3]), "r"(b[0]), "r"(b[1]));
}
__device__ __forceinline__ uint32_t cvt_bf16x2(float a, float b) {   // low=a, high=b
    uint32_t r;
    asm("cvt.rn.bf16x2.f32 %0, %1, %2;" : "=r"(r) : "f"(b), "f"(a));
    return r;
}
__device__ __forceinline__ void split2(float a, float b, uint32_t& h2, uint32_t& l2) {
    h2 = cvt_bf16x2(a, b);
    float af = __uint_as_float(h2 << 16);
    float bf = __uint_as_float(h2 & 0xFFFF0000u);
    l2 = cvt_bf16x2(a - af, b - bf);
}

// ------------------------- prep -------------------------
__global__ void prep_cmb_kernel(const float* __restrict__ mask,
                                const float* __restrict__ bias_table,
                                const int*   __restrict__ rel_index) {
    int idx = blockIdx.x * 256 + threadIdx.x;
    if (idx >= NWIN * NH * NTOK * 56) return;
    int j = idx % 56;
    int rest = idx / 56;
    int i = rest % NTOK;
    int h = (rest / NTOK) % NH;
    int w = rest / (NTOK * NH);
    float v = -1e30f;
    if (j < NTOK)
        v = bias_table[rel_index[i * NTOK + j] * NH + h] + mask[(w * NTOK + i) * NTOK + j];
    g_cmb[idx] = v;
}

// ------------------------- K1/K3: bf16x3 split GEMM via mma.sync -------------------------
#define BSTRIDE   272
#define SM_AHI    0
#define SM_ALO    34816
#define SM_BHI    69632
#define SM_BLO    104448
#define SM_TOTAL  139264
#define DST       129

__device__ __forceinline__ void stage_split(const float* __restrict__ src,  // 128x128 fp32
                                            char* hi, char* lo, int tid) {
    const float4* s4 = (const float4*)src;
    #pragma unroll
    for (int it = 0; it < 16; it++) {
        int i  = tid + it * 256;
        int r  = i >> 5;
        int c4 = (i & 31) * 8;
        float4 v = s4[i];
        uint32_t h0, l0, h1, l1;
        split2(v.x, v.y, h0, l0);
        split2(v.z, v.w, h1, l1);
        ull hp, lp;
        asm("mov.b64 %0, {%1, %2};" : "=l"(hp) : "r"(h0), "r"(h1));
        asm("mov.b64 %0, {%1, %2};" : "=l"(lp) : "r"(l0), "r"(l1));
        *(ull*)(hi + r * BSTRIDE + c4) = hp;
        *(ull*)(lo + r * BSTRIDE + c4) = lp;
    }
}

__global__ __launch_bounds__(256, 1)
void gemm_split_kernel(const float* __restrict__ A,
                       const float* __restrict__ W,
                       const float* __restrict__ bias,
                       int nchunks, int mode,           // 0: qkv scatter, 1: proj->out
                       float* __restrict__ out) {
    extern __shared__ char gsm[];
    char* sAhi = gsm + SM_AHI;
    char* sAlo = gsm + SM_ALO;
    char* sBhi = gsm + SM_BHI;
    char* sBlo = gsm + SM_BLO;
    float* sD  = (float*)(gsm + SM_BHI);

    const int tid = threadIdx.x, lane = tid & 31, wid = tid >> 5;
    const int wm = wid & 3;
    const int wn = wid >> 2;
    const int m0 = blockIdx.x * 128;
    const float* Ap = (mode == 1) ? g_O : A;

    stage_split(Ap + (size_t)m0 * 128, sAhi, sAlo, tid);

    const uint32_t aHiB = smem_u32(sAhi), aLoB = smem_u32(sAlo);
    const uint32_t bHiB = smem_u32(sBhi), bLoB = smem_u32(sBlo);
    uint32_t aOff[2];
    #pragma unroll
    for (int mt = 0; mt < 2; mt++)
        aOff[mt] = (uint32_t)((32 * wm + 16 * mt + (lane & 15)) * BSTRIDE + (lane >> 4) * 16);
    uint32_t bOff[4];
    #pragma unroll
    for (int p = 0; p < 4; p++)
        bOff[p] = (uint32_t)((64 * wn + 16 * p + (lane & 7) + ((lane >> 4) << 3)) * BSTRIDE
                             + ((lane >> 3) & 1) * 16);

    for (int ch = 0; ch < nchunks; ch++) {
        if (ch) __syncthreads();
        stage_split(W + (size_t)ch * 128 * 128, sBhi, sBlo, tid);
        __syncthreads();

        float acc[2][8][4];
        #pragma unroll
        for (int mt = 0; mt < 2; mt++)
            #pragma unroll
            for (int nt = 0; nt < 8; nt++)
                #pragma unroll
                for (int e = 0; e < 4; e++) acc[mt][nt][e] = 0.f;

        #pragma unroll
        for (int kk = 0; kk < 8; kk++) {
            const uint32_t kb = kk * 32;
            uint32_t ah[2][4], al[2][4], bh[4][4], bl[4][4];
            #pragma unroll
            for (int mt = 0; mt < 2; mt++) {
                ldsm4(ah[mt], aHiB + aOff[mt] + kb);
                ldsm4(al[mt], aLoB + aOff[mt] + kb);
            }
            #pragma unroll
            for (int p = 0; p < 4; p++) {
                ldsm4(bh[p], bHiB + bOff[p] + kb);
                ldsm4(bl[p], bLoB + bOff[p] + kb);
            }
            #pragma unroll
            for (int mt = 0; mt < 2; mt++)
                #pragma unroll
                for (int p = 0; p < 4; p++) {
                    mma16816(acc[mt][2 * p],     ah[mt], &bh[p][0]);
                    mma16816(acc[mt][2 * p + 1], ah[mt], &bh[p][2]);
                    mma16816(acc[mt][2 * p],     ah[mt], &bl[p][0]);
                    mma16816(acc[mt][2 * p + 1], ah[mt], &bl[p][2]);
                    mma16816(acc[mt][2 * p],     al[mt], &bh[p][0]);
                    mma16816(acc[mt][2 * p + 1], al[mt], &bh[p][2]);
                }
        }
        __syncthreads();

        #pragma unroll
        for (int mt = 0; mt < 2; mt++) {
            int r0 = 32 * wm + 16 * mt + (lane >> 2);
            #pragma unroll
            for (int nt = 0; nt < 8; nt++) {
                int n = 64 * wn + 8 * nt + 2 * (lane & 3);
                sD[r0 * DST + n]           = acc[mt][nt][0];
                sD[r0 * DST + n + 1]       = acc[mt][nt][1];
                sD[(r0 + 8) * DST + n]     = acc[mt][nt][2];
                sD[(r0 + 8) * DST + n + 1] = acc[mt][nt][3];
            }
        }
        __syncthreads();

        const float* bb = bias + ch * 128;
        if (mode == 0) {
            if (ch < 2) {
                uint32_t* gh = ch ? g_kh : g_qh;
                uint32_t* gl = ch ? g_kl : g_ql;
                float scl = ch ? 1.f : QKSCALE;
                #pragma unroll 4
                for (int it = 0; it < 32; it++) {
                    int i  = tid + it * 256;
                    int cp = i & 63, m = i >> 6;
                    float a = (sD[m * DST + 2 * cp]     + __ldg(bb + 2 * cp))     * scl;
                    float b = (sD[m * DST + 2 * cp + 1] + __ldg(bb + 2 * cp + 1)) * scl;
                    uint32_t h2, l2; split2(a, b, h2, l2);
                    unsigned gm = (unsigned)(m0 + m);
                    unsigned win = gm / 49u, tok = gm - win * 49u;
                    size_t dst = ((size_t)win * 49 + tok) * 64 + cp;
                    gh[dst] = h2; gl[dst] = l2;
                }
            } else {
                #pragma unroll 4
                for (int it = 0; it < 64; it++) {
                    int i = tid + it * 256;
                    int c = i >> 7, m = i & 127;
                    float val = sD[m * DST + c] + __ldg(bb + c);
                    uint32_t h2, l2; split2(val, 0.f, h2, l2);
                    unsigned gm = (unsigned)(m0 + m);
                    unsigned win = gm / 49u, tok = gm - win * 49u;
                    size_t dst = ((size_t)win * 128 + c) * 64 + tok;
                    g_vh[dst] = (unsigned short)(h2 & 0xFFFFu);
                    g_vl[dst] = (unsigned short)(l2 & 0xFFFFu);
                }
            }
        } else {
            #pragma unroll 4
            for (int it = 0; it < 64; it++) {
                int i = tid + it * 256;
                int r = i >> 7, c = i & 127;
                out[(size_t)(m0 + r) * 128 + c] = sD[r * DST + c] + __ldg(bb + c);
            }
        }
    }
}

// ------------------------- K2: tensor-core attention per (window, head) -------------------------
// smem: q/k hi+lo [64 rows][32 bf16] stride 80B; v hi+lo [32 c][64 j] stride 144B; cmb [64][56] fp32
#define QKS 80
#define VS  144

__global__ __launch_bounds__(128, 5)
void attn_kernel() {
    __shared__ __align__(16) char s_qh[64 * QKS], s_ql[64 * QKS];
    __shared__ __align__(16) char s_kh[64 * QKS], s_kl[64 * QKS];
    __shared__ __align__(16) char s_vh[32 * VS],  s_vl[32 * VS];
    __shared__ __align__(16) float s_cmb[64 * 56];   // reused as O bounce (64*33 fits)

    const int tid = threadIdx.x, w = tid >> 5, lane = tid & 31;
    const int win = blockIdx.x >> 2, h = blockIdx.x & 3;

    // ---- staging ----
    {
        const uint32_t* gqh = g_qh + ((size_t)win * 49) * 64 + h * 16;
        const uint32_t* gql = g_ql + ((size_t)win * 49) * 64 + h * 16;
        const uint32_t* gkh = g_kh + ((size_t)win * 49) * 64 + h * 16;
        const uint32_t* gkl = g_kl + ((size_t)win * 49) * 64 + h * 16;
        #pragma unroll
        for (int it = 0; it < 8; it++) {
            int idx = tid + it * 128;          // 64 rows x 16 dpairs
            int r = idx >> 4, dp = idx & 15;
            uint32_t vqh = 0, vql = 0, vkh = 0, vkl = 0;
            if (r < 49) {
                size_t off = (size_t)r * 64 + dp;
                vqh = gqh[off]; vql = gql[off]; vkh = gkh[off]; vkl = gkl[off];
            }
            *(uint32_t*)(s_qh + r * QKS + dp * 4) = vqh;
            *(uint32_t*)(s_ql + r * QKS + dp * 4) = vql;
            *(uint32_t*)(s_kh + r * QKS + dp * 4) = vkh;
            *(uint32_t*)(s_kl + r * QKS + dp * 4) = vkl;
        }
        const uint32_t* gvh = (const uint32_t*)g_vh + ((size_t)win * 128 + h * 32) * 32;
        const uint32_t* gvl = (const uint32_t*)g_vl + ((size_t)win * 128 + h * 32) * 32;
        #pragma unroll
        for (int it = 0; it < 8; it++) {
            int idx = tid + it * 128;          // 32 c x 32 jpairs (j pad zeros from .bss)
            int c = idx >> 5, jp = idx & 31;
            *(uint32_t*)(s_vh + c * VS + jp * 4) = gvh[(size_t)c * 32 + jp];
            *(uint32_t*)(s_vl + c * VS + jp * 4) = gvl[(size_t)c * 32 + jp];
        }
        const float* gc = g_cmb + (size_t)((win & (NWIN - 1)) * NH + h) * (49 * 56);
        #pragma unroll
        for (int it = 0; it < 28; it++) {
            int idx = tid + it * 128;          // 64 x 56
            int i = idx / 56;
            s_cmb[idx] = (i < 49) ? gc[idx] : 0.f;
        }
    }
    __syncthreads();

    // ---- S = q k^T (2-split bf16) ----
    const uint32_t qhB = smem_u32(s_qh) + (uint32_t)((16 * w + (lane & 15)) * QKS + (lane >> 4) * 16);
    const uint32_t qlB = smem_u32(s_ql) + (uint32_t)((16 * w + (lane & 15)) * QKS + (lane >> 4) * 16);
    const uint32_t kRow = (uint32_t)(((lane & 7) + ((lane >> 4) << 3)) * QKS + ((lane >> 3) & 1) * 16);
    const uint32_t khB = smem_u32(s_kh) + kRow;
    const uint32_t klB = smem_u32(s_kl) + kRow;

    float S[7][4];
    #pragma unroll
    for (int t = 0; t < 7; t++)
        #pragma unroll
        for (int e = 0; e < 4; e++) S[t][e] = 0.f;

    #pragma unroll
    for (int s = 0; s < 2; s++) {
        uint32_t qh_f[4], ql_f[4];
        ldsm4(qh_f, qhB + s * 32);
        ldsm4(ql_f, qlB + s * 32);
        #pragma unroll
        for (int p = 0; p < 4; p++) {
            uint32_t kh_f[4], kl_f[4];
            ldsm4(kh_f, khB + p * (16 * QKS) + s * 32);
            ldsm4(kl_f, klB + p * (16 * QKS) + s * 32);
            mma16816(S[2 * p], qh_f, &kh_f[0]);
            mma16816(S[2 * p], qh_f, &kl_f[0]);
            mma16816(S[2 * p], ql_f, &kh_f[0]);
            if (p < 3) {
                mma16816(S[2 * p + 1], qh_f, &kh_f[2]);
                mma16816(S[2 * p + 1], qh_f, &kl_f[2]);
                mma16816(S[2 * p + 1], ql_f, &kh_f[2]);
            }
        }
    }

    // ---- + (bias+mask), softmax in registers ----
    const int gr = lane >> 2, ci = lane & 3;
    const int r0 = 16 * w + gr;                 // rows r0, r0+8
    float mx0 = -1e30f, mx1 = -1e30f;
    #pragma unroll
    for (int t = 0; t < 7; t++) {
        int c = 8 * t + 2 * ci;
        S[t][0] += s_cmb[r0 * 56 + c];
        S[t][1] += s_cmb[r0 * 56 + c + 1];
        S[t][2] += s_cmb[(r0 + 8) * 56 + c];
        S[t][3] += s_cmb[(r0 + 8) * 56 + c + 1];
        mx0 = fmaxf(mx0, fmaxf(S[t][0], S[t][1]));
        mx1 = fmaxf(mx1, fmaxf(S[t][2], S[t][3]));
    }
    #pragma unroll
    for (int o = 1; o <= 2; o <<= 1) {
        mx0 = fmaxf(mx0, __shfl_xor_sync(0xffffffffu, mx0, o));
        mx1 = fmaxf(mx1, __shfl_xor_sync(0xffffffffu, mx1, o));
    }
    float sm0 = 0.f, sm1 = 0.f;
    #pragma unroll
    for (int t = 0; t < 7; t++) {
        S[t][0] = __expf(S[t][0] - mx0); sm0 += S[t][0];
        S[t][1] = __expf(S[t][1] - mx0); sm0 += S[t][1];
        S[t][2] = __expf(S[t][2] - mx1); sm1 += S[t][2];
        S[t][3] = __expf(S[t][3] - mx1); sm1 += S[t][3];
    }
    #pragma unroll
    for (int o = 1; o <= 2; o <<= 1) {
        sm0 += __shfl_xor_sync(0xffffffffu, sm0, o);
        sm1 += __shfl_xor_sync(0xffffffffu, sm1, o);
    }
    float inv0 = 1.f / sm0, inv1 = 1.f / sm1;
    #pragma unroll
    for (int t = 0; t < 7; t++) {
        S[t][0] *= inv0; S[t][1] *= inv0;
        S[t][2] *= inv1; S[t][3] *= inv1;
    }

    // ---- O = P V (2-split: Ph*Vh + Pl*Vh + Ph*Vl) ----
    const uint32_t vRow = (uint32_t)(((lane & 7) + ((lane >> 4) << 3)) * VS + ((lane >> 3) & 1) * 16);
    const uint32_t vhB = smem_u32(s_vh) + vRow;
    const uint32_t vlB = smem_u32(s_vl) + vRow;

    float O[4][4];
    #pragma unroll
    for (int t = 0; t < 4; t++)
        #pragma unroll
        for (int e = 0; e < 4; e++) O[t][e] = 0.f;

    #pragma unroll
    for (int s = 0; s < 4; s++) {
        int t0 = 2 * s, t1 = 2 * s + 1;
        uint32_t aH[4], aL[4];
        split2(S[t0][0], S[t0][1], aH[0], aL[0]);
        split2(S[t0][2], S[t0][3], aH[1], aL[1]);
        if (t1 < 7) {
            split2(S[t1][0], S[t1][1], aH[2], aL[2]);
            split2(S[t1][2], S[t1][3], aH[3], aL[3]);
        } else {
            aH[2] = aH[3] = aL[2] = aL[3] = 0u;
        }
        #pragma unroll
        for (int g = 0; g < 2; g++) {
            uint32_t vh_f[4], vl_f[4];
            ldsm4(vh_f, vhB + g * (16 * VS) + s * 32);
            ldsm4(vl_f, vlB + g * (16 * VS) + s * 32);
            mma16816(O[2 * g],     aH, &vh_f[0]);
            mma16816(O[2 * g + 1], aH, &vh_f[2]);
            mma16816(O[2 * g],     aL, &vh_f[0]);
            mma16816(O[2 * g + 1], aL, &vh_f[2]);
            mma16816(O[2 * g],     aH, &vl_f[0]);
            mma16816(O[2 * g + 1], aH, &vl_f[2]);
        }
    }

    // ---- store O via smem bounce (reuse cmb region) ----
    __syncthreads();                       // all cmb reads done
    float* O_s = s_cmb;                    // stride 33
    #pragma unroll
    for (int t = 0; t < 4; t++) {
        int c = 8 * t + 2 * ci;
        if (r0 < 49) {
            O_s[r0 * 33 + c]     = O[t][0];
            O_s[r0 * 33 + c + 1] = O[t][1];
        }
        if (r0 + 8 < 49) {
            O_s[(r0 + 8) * 33 + c]     = O[t][2];
            O_s[(r0 + 8) * 33 + c + 1] = O[t][3];
        }
    }
    __syncthreads();
    #pragma unroll
    for (int it = 0; it < 13; it++) {
        int idx = tid + it * 128;
        if (idx < 49 * 32) {
            int i = idx >> 5, c = idx & 31;
            g_O[((size_t)win * 49 + i) * 128 + h * 32 + c] = O_s[i * 33 + c];
        }
    }
}

// ------------------------- launch -------------------------
extern "C" void kernel_launch(void* const* d_in, const int* in_sizes, int n_in,
                              void* d_out, int out_size) {
    const float* x          = (const float*)d_in[0];
    const float* mask       = (const float*)d_in[1];
    const float* qkv_w      = (const float*)d_in[2];
    const float* qkv_b      = (const float*)d_in[3];
    const float* proj_w     = (const float*)d_in[4];
    const float* proj_b     = (const float*)d_in[5];
    const float* bias_table = (const float*)d_in[6];
    const int*   rel_index  = (const int*)d_in[7];
    float* out = (float*)d_out;

    cudaFuncSetAttribute(gemm_split_kernel,
                         cudaFuncAttributeMaxDynamicSharedMemorySize, SM_TOTAL);

    int ctot = NWIN * NH * NTOK * 56;
    prep_cmb_kernel<<<(ctot + 255) / 256, 256>>>(mask, bias_table, rel_index);

    // K1: qkv GEMM -> split q/k (row-major) + v (transposed)
    gemm_split_kernel<<<MTILES, 256, SM_TOTAL>>>(x, qkv_w, qkv_b, 3, 0, out);
    // K2: tensor-core attention -> g_O
    attn_kernel<<<NWINDOWS * NH, 128>>>();
    // K3: proj GEMM -> out
    gemm_split_kernel<<<MTILES, 256, SM_TOTAL>>>(nullptr, proj_w, proj_b, 1, 1, out);
}

// round 12
// speedup vs baseline: 3.3247x; 1.0034x over previous
#include <cuda_runtime.h>
#include <cuda_bf16.h>
#include <cstdint>

// Swin WindowAttention, 4-kernel pipeline, all-tensor-core (sm_100-safe mma.sync):
//   prep: bias+mask combined (stride 56, -1e30 pad for j>=49)
//   K1: bf16x3-split GEMM qkv = x@Wqkv^T + b -> q,k bf16 hi/lo [win][tok][64 pairs]; v hi/lo transposed [win][c][64]
//   K2: tensor-core attention per (window, head): S via mma (2-split), reg softmax, PV via mma (2-split)
//   K3: bf16x3-split GEMM out = O@Wproj^T + b

#define NTOK     49
#define DIMC     128
#define NH       4
#define NWIN     64
#define NWINDOWS 4096
#define MROWS    (NWINDOWS * NTOK)   // 200704
#define MTILES   (MROWS / 128)       // 1568
#define QKSCALE  0.17677669529663687f

typedef unsigned long long ull;

// ------------------------- device globals (scratch, zero-init .bss) -------------------------
__device__ uint32_t g_qh[(size_t)NWINDOWS * NTOK * 64];   // bf16x2 pairs, [win][tok][64]
__device__ uint32_t g_ql[(size_t)NWINDOWS * NTOK * 64];
__device__ uint32_t g_kh[(size_t)NWINDOWS * NTOK * 64];
__device__ uint32_t g_kl[(size_t)NWINDOWS * NTOK * 64];
__device__ unsigned short g_vh[(size_t)NWINDOWS * 128 * 64];  // bf16, [win][c][64] (j pad 49..63 stays 0)
__device__ unsigned short g_vl[(size_t)NWINDOWS * 128 * 64];
__device__ float g_O [(size_t)MROWS * DIMC];              // [row][c]
__device__ float g_cmb[NWIN * NH * NTOK * 56];            // [w][h][i][56], j>=49 -> -1e30

// ------------------------- helpers -------------------------
__device__ __forceinline__ uint32_t smem_u32(const void* p) {
    uint32_t a;
    asm("{ .reg .u64 t; cvta.to.shared.u64 t, %1; cvt.u32.u64 %0, t; }" : "=r"(a) : "l"(p));
    return a;
}
__device__ __forceinline__ void ldsm4(uint32_t* r, uint32_t addr) {
    asm volatile("ldmatrix.sync.aligned.m8n8.x4.shared.b16 {%0,%1,%2,%3}, [%4];"
                 : "=r"(r[0]), "=r"(r[1]), "=r"(r[2]), "=r"(r[3]) : "r"(addr));
}
__device__ __forceinline__ void mma16816(float* d, const uint32_t* a, const uint32_t* b) {
    asm volatile("mma.sync.aligned.m16n8k16.row.col.f32.bf16.bf16.f32 "
                 "{%0,%1,%2,%3}, {%4,%5,%6,%7}, {%8,%9}, {%0,%1,%2,%3};"
                 : "+f"(d[0]), "+f"(d[1]), "+f"(d[2]), "+f"(d[3])
                 : "r"(a[0]), "r"(a[1]), "r"(a[2]), "r"(a[3]), "r"(b[0]), "r"(b[1]));
}
__device__ __forceinline__ uint32_t cvt_bf16x2(float a, float b) {   // low=a, high=b
    uint32_t r;
    asm("cvt.rn.bf16x2.f32 %0, %1, %2;" : "=r"(r) : "f"(b), "f"(a));
    return r;
}
__device__ __forceinline__ void split2(float a, float b, uint32_t& h2, uint32_t& l2) {
    h2 = cvt_bf16x2(a, b);
    float af = __uint_as_float(h2 << 16);
    float bf = __uint_as_float(h2 & 0xFFFF0000u);
    l2 = cvt_bf16x2(a - af, b - bf);
}

// ------------------------- prep -------------------------
__global__ void prep_cmb_kernel(const float* __restrict__ mask,
                                const float* __restrict__ bias_table,
                                const int*   __restrict__ rel_index) {
    int idx = blockIdx.x * 256 + threadIdx.x;
    if (idx >= NWIN * NH * NTOK * 56) return;
    int j = idx % 56;
    int rest = idx / 56;
    int i = rest % NTOK;
    int h = (rest / NTOK) % NH;
    int w = rest / (NTOK * NH);
    float v = -1e30f;
    if (j < NTOK)
        v = bias_table[rel_index[i * NTOK + j] * NH + h] + mask[(w * NTOK + i) * NTOK + j];
    g_cmb[idx] = v;
}

// ------------------------- K1/K3: bf16x3 split GEMM via mma.sync -------------------------
#define BSTRIDE   272
#define SM_AHI    0
#define SM_ALO    34816
#define SM_BHI    69632
#define SM_BLO    104448
#define SM_TOTAL  139264
#define DST       129

__device__ __forceinline__ void stage_split(const float* __restrict__ src,  // 128x128 fp32
                                            char* hi, char* lo, int tid) {
    const float4* s4 = (const float4*)src;
    #pragma unroll
    for (int it = 0; it < 16; it++) {
        int i  = tid + it * 256;
        int r  = i >> 5;
        int c4 = (i & 31) * 8;
        float4 v = s4[i];
        uint32_t h0, l0, h1, l1;
        split2(v.x, v.y, h0, l0);
        split2(v.z, v.w, h1, l1);
        ull hp, lp;
        asm("mov.b64 %0, {%1, %2};" : "=l"(hp) : "r"(h0), "r"(h1));
        asm("mov.b64 %0, {%1, %2};" : "=l"(lp) : "r"(l0), "r"(l1));
        *(ull*)(hi + r * BSTRIDE + c4) = hp;
        *(ull*)(lo + r * BSTRIDE + c4) = lp;
    }
}

__global__ __launch_bounds__(256, 1)
void gemm_split_kernel(const float* __restrict__ A,
                       const float* __restrict__ W,
                       const float* __restrict__ bias,
                       int nchunks, int mode,           // 0: qkv scatter, 1: proj->out
                       float* __restrict__ out) {
    extern __shared__ char gsm[];
    char* sAhi = gsm + SM_AHI;
    char* sAlo = gsm + SM_ALO;
    char* sBhi = gsm + SM_BHI;
    char* sBlo = gsm + SM_BLO;
    float* sD  = (float*)(gsm + SM_BHI);

    const int tid = threadIdx.x, lane = tid & 31, wid = tid >> 5;
    const int wm = wid & 3;
    const int wn = wid >> 2;
    const int m0 = blockIdx.x * 128;
    const float* Ap = (mode == 1) ? g_O : A;

    stage_split(Ap + (size_t)m0 * 128, sAhi, sAlo, tid);

    const uint32_t aHiB = smem_u32(sAhi), aLoB = smem_u32(sAlo);
    const uint32_t bHiB = smem_u32(sBhi), bLoB = smem_u32(sBlo);
    uint32_t aOff[2];
    #pragma unroll
    for (int mt = 0; mt < 2; mt++)
        aOff[mt] = (uint32_t)((32 * wm + 16 * mt + (lane & 15)) * BSTRIDE + (lane >> 4) * 16);
    uint32_t bOff[4];
    #pragma unroll
    for (int p = 0; p < 4; p++)
        bOff[p] = (uint32_t)((64 * wn + 16 * p + (lane & 7) + ((lane >> 4) << 3)) * BSTRIDE
                             + ((lane >> 3) & 1) * 16);

    for (int ch = 0; ch < nchunks; ch++) {
        if (ch) __syncthreads();
        stage_split(W + (size_t)ch * 128 * 128, sBhi, sBlo, tid);
        __syncthreads();

        float acc[2][8][4];
        #pragma unroll
        for (int mt = 0; mt < 2; mt++)
            #pragma unroll
            for (int nt = 0; nt < 8; nt++)
                #pragma unroll
                for (int e = 0; e < 4; e++) acc[mt][nt][e] = 0.f;

        #pragma unroll
        for (int kk = 0; kk < 8; kk++) {
            const uint32_t kb = kk * 32;
            uint32_t ah[2][4], al[2][4], bh[4][4], bl[4][4];
            #pragma unroll
            for (int mt = 0; mt < 2; mt++) {
                ldsm4(ah[mt], aHiB + aOff[mt] + kb);
                ldsm4(al[mt], aLoB + aOff[mt] + kb);
            }
            #pragma unroll
            for (int p = 0; p < 4; p++) {
                ldsm4(bh[p], bHiB + bOff[p] + kb);
                ldsm4(bl[p], bLoB + bOff[p] + kb);
            }
            #pragma unroll
            for (int mt = 0; mt < 2; mt++)
                #pragma unroll
                for (int p = 0; p < 4; p++) {
                    mma16816(acc[mt][2 * p],     ah[mt], &bh[p][0]);
                    mma16816(acc[mt][2 * p + 1], ah[mt], &bh[p][2]);
                    mma16816(acc[mt][2 * p],     ah[mt], &bl[p][0]);
                    mma16816(acc[mt][2 * p + 1], ah[mt], &bl[p][2]);
                    mma16816(acc[mt][2 * p],     al[mt], &bh[p][0]);
                    mma16816(acc[mt][2 * p + 1], al[mt], &bh[p][2]);
                }
        }
        __syncthreads();

        #pragma unroll
        for (int mt = 0; mt < 2; mt++) {
            int r0 = 32 * wm + 16 * mt + (lane >> 2);
            #pragma unroll
            for (int nt = 0; nt < 8; nt++) {
                int n = 64 * wn + 8 * nt + 2 * (lane & 3);
                sD[r0 * DST + n]           = acc[mt][nt][0];
                sD[r0 * DST + n + 1]       = acc[mt][nt][1];
                sD[(r0 + 8) * DST + n]     = acc[mt][nt][2];
                sD[(r0 + 8) * DST + n + 1] = acc[mt][nt][3];
            }
        }
        __syncthreads();

        const float* bb = bias + ch * 128;
        if (mode == 0) {
            if (ch < 2) {
                uint32_t* gh = ch ? g_kh : g_qh;
                uint32_t* gl = ch ? g_kl : g_ql;
                float scl = ch ? 1.f : QKSCALE;
                #pragma unroll 4
                for (int it = 0; it < 32; it++) {
                    int i  = tid + it * 256;
                    int cp = i & 63, m = i >> 6;
                    float a = (sD[m * DST + 2 * cp]     + __ldg(bb + 2 * cp))     * scl;
                    float b = (sD[m * DST + 2 * cp + 1] + __ldg(bb + 2 * cp + 1)) * scl;
                    uint32_t h2, l2; split2(a, b, h2, l2);
                    unsigned gm = (unsigned)(m0 + m);
                    unsigned win = gm / 49u, tok = gm - win * 49u;
                    size_t dst = ((size_t)win * 49 + tok) * 64 + cp;
                    gh[dst] = h2; gl[dst] = l2;
                }
            } else {
                #pragma unroll 4
                for (int it = 0; it < 64; it++) {
                    int i = tid + it * 256;
                    int c = i >> 7, m = i & 127;
                    float val = sD[m * DST + c] + __ldg(bb + c);
                    uint32_t h2, l2; split2(val, 0.f, h2, l2);
                    unsigned gm = (unsigned)(m0 + m);
                    unsigned win = gm / 49u, tok = gm - win * 49u;
                    size_t dst = ((size_t)win * 128 + c) * 64 + tok;
                    g_vh[dst] = (unsigned short)(h2 & 0xFFFFu);
                    g_vl[dst] = (unsigned short)(l2 & 0xFFFFu);
                }
            }
        } else {
            #pragma unroll 4
            for (int it = 0; it < 64; it++) {
                int i = tid + it * 256;
                int r = i >> 7, c = i & 127;
                out[(size_t)(m0 + r) * 128 + c] = sD[r * DST + c] + __ldg(bb + c);
            }
        }
    }
}

// ------------------------- K2: tensor-core attention per (window, head) -------------------------
// smem: q/k hi+lo [64 rows][32 bf16] stride 80B; v hi+lo [32 c][64 j] stride 144B; cmb [64][56] fp32
#define QKS 80
#define VS  144

__global__ __launch_bounds__(128)
void attn_kernel() {
    __shared__ __align__(16) char s_qh[64 * QKS], s_ql[64 * QKS];
    __shared__ __align__(16) char s_kh[64 * QKS], s_kl[64 * QKS];
    __shared__ __align__(16) char s_vh[32 * VS],  s_vl[32 * VS];
    __shared__ __align__(16) float s_cmb[64 * 56];   // reused as O bounce (64*33 fits)

    const int tid = threadIdx.x, w = tid >> 5, lane = tid & 31;
    const int win = blockIdx.x >> 2, h = blockIdx.x & 3;

    // ---- staging ----
    {
        const uint32_t* gqh = g_qh + ((size_t)win * 49) * 64 + h * 16;
        const uint32_t* gql = g_ql + ((size_t)win * 49) * 64 + h * 16;
        const uint32_t* gkh = g_kh + ((size_t)win * 49) * 64 + h * 16;
        const uint32_t* gkl = g_kl + ((size_t)win * 49) * 64 + h * 16;
        #pragma unroll
        for (int it = 0; it < 8; it++) {
            int idx = tid + it * 128;          // 64 rows x 16 dpairs
            int r = idx >> 4, dp = idx & 15;
            uint32_t vqh = 0, vql = 0, vkh = 0, vkl = 0;
            if (r < 49) {
                size_t off = (size_t)r * 64 + dp;
                vqh = gqh[off]; vql = gql[off]; vkh = gkh[off]; vkl = gkl[off];
            }
            *(uint32_t*)(s_qh + r * QKS + dp * 4) = vqh;
            *(uint32_t*)(s_ql + r * QKS + dp * 4) = vql;
            *(uint32_t*)(s_kh + r * QKS + dp * 4) = vkh;
            *(uint32_t*)(s_kl + r * QKS + dp * 4) = vkl;
        }
        const uint32_t* gvh = (const uint32_t*)g_vh + ((size_t)win * 128 + h * 32) * 32;
        const uint32_t* gvl = (const uint32_t*)g_vl + ((size_t)win * 128 + h * 32) * 32;
        #pragma unroll
        for (int it = 0; it < 8; it++) {
            int idx = tid + it * 128;          // 32 c x 32 jpairs (j pad zeros from .bss)
            int c = idx >> 5, jp = idx & 31;
            *(uint32_t*)(s_vh + c * VS + jp * 4) = gvh[(size_t)c * 32 + jp];
            *(uint32_t*)(s_vl + c * VS + jp * 4) = gvl[(size_t)c * 32 + jp];
        }
        const float* gc = g_cmb + (size_t)((win & (NWIN - 1)) * NH + h) * (49 * 56);
        #pragma unroll
        for (int it = 0; it < 28; it++) {
            int idx = tid + it * 128;          // 64 x 56
            int i = idx / 56;
            s_cmb[idx] = (i < 49) ? gc[idx] : 0.f;
        }
    }
    __syncthreads();

    // ---- S = q k^T (2-split bf16) ----
    const uint32_t qhB = smem_u32(s_qh) + (uint32_t)((16 * w + (lane & 15)) * QKS + (lane >> 4) * 16);
    const uint32_t qlB = smem_u32(s_ql) + (uint32_t)((16 * w + (lane & 15)) * QKS + (lane >> 4) * 16);
    const uint32_t kRow = (uint32_t)(((lane & 7) + ((lane >> 4) << 3)) * QKS + ((lane >> 3) & 1) * 16);
    const uint32_t khB = smem_u32(s_kh) + kRow;
    const uint32_t klB = smem_u32(s_kl) + kRow;

    float S[7][4];
    #pragma unroll
    for (int t = 0; t < 7; t++)
        #pragma unroll
        for (int e = 0; e < 4; e++) S[t][e] = 0.f;

    #pragma unroll
    for (int s = 0; s < 2; s++) {
        uint32_t qh_f[4], ql_f[4];
        ldsm4(qh_f, qhB + s * 32);
        ldsm4(ql_f, qlB + s * 32);
        #pragma unroll
        for (int p = 0; p < 4; p++) {
            uint32_t kh_f[4], kl_f[4];
            ldsm4(kh_f, khB + p * (16 * QKS) + s * 32);
            ldsm4(kl_f, klB + p * (16 * QKS) + s * 32);
            mma16816(S[2 * p], qh_f, &kh_f[0]);
            mma16816(S[2 * p], qh_f, &kl_f[0]);
            mma16816(S[2 * p], ql_f, &kh_f[0]);
            if (p < 3) {
                mma16816(S[2 * p + 1], qh_f, &kh_f[2]);
                mma16816(S[2 * p + 1], qh_f, &kl_f[2]);
                mma16816(S[2 * p + 1], ql_f, &kh_f[2]);
            }
        }
    }

    // ---- + (bias+mask), softmax in registers ----
    const int gr = lane >> 2, ci = lane & 3;
    const int r0 = 16 * w + gr;                 // rows r0, r0+8
    float mx0 = -1e30f, mx1 = -1e30f;
    #pragma unroll
    for (int t = 0; t < 7; t++) {
        int c = 8 * t + 2 * ci;
        S[t][0] += s_cmb[r0 * 56 + c];
        S[t][1] += s_cmb[r0 * 56 + c + 1];
        S[t][2] += s_cmb[(r0 + 8) * 56 + c];
        S[t][3] += s_cmb[(r0 + 8) * 56 + c + 1];
        mx0 = fmaxf(mx0, fmaxf(S[t][0], S[t][1]));
        mx1 = fmaxf(mx1, fmaxf(S[t][2], S[t][3]));
    }
    #pragma unroll
    for (int o = 1; o <= 2; o <<= 1) {
        mx0 = fmaxf(mx0, __shfl_xor_sync(0xffffffffu, mx0, o));
        mx1 = fmaxf(mx1, __shfl_xor_sync(0xffffffffu, mx1, o));
    }
    float sm0 = 0.f, sm1 = 0.f;
    #pragma unroll
    for (int t = 0; t < 7; t++) {
        S[t][0] = __expf(S[t][0] - mx0); sm0 += S[t][0];
        S[t][1] = __expf(S[t][1] - mx0); sm0 += S[t][1];
        S[t][2] = __expf(S[t][2] - mx1); sm1 += S[t][2];
        S[t][3] = __expf(S[t][3] - mx1); sm1 += S[t][3];
    }
    #pragma unroll
    for (int o = 1; o <= 2; o <<= 1) {
        sm0 += __shfl_xor_sync(0xffffffffu, sm0, o);
        sm1 += __shfl_xor_sync(0xffffffffu, sm1, o);
    }
    float inv0 = 1.f / sm0, inv1 = 1.f / sm1;
    #pragma unroll
    for (int t = 0; t < 7; t++) {
        S[t][0] *= inv0; S[t][1] *= inv0;
        S[t][2] *= inv1; S[t][3] *= inv1;
    }

    // ---- O = P V (2-split: Ph*Vh + Pl*Vh + Ph*Vl) ----
    const uint32_t vRow = (uint32_t)(((lane & 7) + ((lane >> 4) << 3)) * VS + ((lane >> 3) & 1) * 16);
    const uint32_t vhB = smem_u32(s_vh) + vRow;
    const uint32_t vlB = smem_u32(s_vl) + vRow;

    float O[4][4];
    #pragma unroll
    for (int t = 0; t < 4; t++)
        #pragma unroll
        for (int e = 0; e < 4; e++) O[t][e] = 0.f;

    #pragma unroll
    for (int s = 0; s < 4; s++) {
        int t0 = 2 * s, t1 = 2 * s + 1;
        uint32_t aH[4], aL[4];
        split2(S[t0][0], S[t0][1], aH[0], aL[0]);
        split2(S[t0][2], S[t0][3], aH[1], aL[1]);
        if (t1 < 7) {
            split2(S[t1][0], S[t1][1], aH[2], aL[2]);
            split2(S[t1][2], S[t1][3], aH[3], aL[3]);
        } else {
            aH[2] = aH[3] = aL[2] = aL[3] = 0u;
        }
        #pragma unroll
        for (int g = 0; g < 2; g++) {
            uint32_t vh_f[4], vl_f[4];
            ldsm4(vh_f, vhB + g * (16 * VS) + s * 32);
            ldsm4(vl_f, vlB + g * (16 * VS) + s * 32);
            mma16816(O[2 * g],     aH, &vh_f[0]);
            mma16816(O[2 * g + 1], aH, &vh_f[2]);
            mma16816(O[2 * g],     aL, &vh_f[0]);
            mma16816(O[2 * g + 1], aL, &vh_f[2]);
            mma16816(O[2 * g],     aH, &vl_f[0]);
            mma16816(O[2 * g + 1], aH, &vl_f[2]);
        }
    }

    // ---- store O via smem bounce (reuse cmb region) ----
    __syncthreads();                       // all cmb reads done
    float* O_s = s_cmb;                    // stride 33
    #pragma unroll
    for (int t = 0; t < 4; t++) {
        int c = 8 * t + 2 * ci;
        if (r0 < 49) {
            O_s[r0 * 33 + c]     = O[t][0];
            O_s[r0 * 33 + c + 1] = O[t][1];
        }
        if (r0 + 8 < 49) {
            O_s[(r0 + 8) * 33 + c]     = O[t][2];
            O_s[(r0 + 8) * 33 + c + 1] = O[t][3];
        }
    }
    __syncthreads();
    #pragma unroll
    for (int it = 0; it < 13; it++) {
        int idx = tid + it * 128;
        if (idx < 49 * 32) {
            int i = idx >> 5, c = idx & 31;
            g_O[((size_t)win * 49 + i) * 128 + h * 32 + c] = O_s[i * 33 + c];
        }
    }
}

// ------------------------- launch -------------------------
extern "C" void kernel_launch(void* const* d_in, const int* in_sizes, int n_in,
                              void* d_out, int out_size) {
    const float* x          = (const float*)d_in[0];
    const float* mask       = (const float*)d_in[1];
    const float* qkv_w      = (const float*)d_in[2];
    const float* qkv_b      = (const float*)d_in[3];
    const float* proj_w     = (const float*)d_in[4];
    const float* proj_b     = (const float*)d_in[5];
    const float* bias_table = (const float*)d_in[6];
    const int*   rel_index  = (const int*)d_in[7];
    float* out = (float*)d_out;

    cudaFuncSetAttribute(gemm_split_kernel,
                         cudaFuncAttributeMaxDynamicSharedMemorySize, SM_TOTAL);

    int ctot = NWIN * NH * NTOK * 56;
    prep_cmb_kernel<<<(ctot + 255) / 256, 256>>>(mask, bias_table, rel_index);

    // K1: qkv GEMM -> split q/k (row-major) + v (transposed)
    gemm_split_kernel<<<MTILES, 256, SM_TOTAL>>>(x, qkv_w, qkv_b, 3, 0, out);
    // K2: tensor-core attention -> g_O
    attn_kernel<<<NWINDOWS * NH, 128>>>();
    // K3: proj GEMM -> out
    gemm_split_kernel<<<MTILES, 256, SM_TOTAL>>>(nullptr, proj_w, proj_b, 1, 1, out);
}